// round 14
// baseline (speedup 1.0000x reference)
#include <cuda_runtime.h>
#include <cuda_bf16.h>
#include <math.h>
#include <stdint.h>

typedef __nv_bfloat16 bf16;

// ---------------- problem constants ----------------
#define B_  4
#define L_  2048
#define D_  1024
#define H_  16
#define HD_ 64
#define M_  (B_ * L_)          // 8192 rows

// ---------------- scratch (device globals; no allocs allowed) ----------------
__device__ __align__(256) bf16 g_xh[(size_t)M_ * D_];
__device__ __align__(256) bf16 g_xl[(size_t)M_ * D_];
__device__ __align__(256) bf16 g_wh[4 * (size_t)D_ * D_];
__device__ __align__(256) bf16 g_wl[4 * (size_t)D_ * D_];
__device__ __align__(256) bf16 g_qkvh[3 * (size_t)M_ * D_];
__device__ __align__(256) bf16 g_qkvl[3 * (size_t)M_ * D_];
__device__ __align__(256) bf16 g_oh[(size_t)M_ * D_];
__device__ __align__(256) bf16 g_ol[(size_t)M_ * D_];
__device__ float g_rcos[L_ * 32];
__device__ float g_rsin[L_ * 32];

// ---------------- base-ISA mma/ldmatrix/cp.async helpers ----------------
__device__ __forceinline__ void mma16816(float* c, const uint32_t* a,
                                         const uint32_t* b) {
    asm volatile(
        "mma.sync.aligned.m16n8k16.row.col.f32.bf16.bf16.f32 "
        "{%0,%1,%2,%3}, {%4,%5,%6,%7}, {%8,%9}, {%0,%1,%2,%3};"
        : "+f"(c[0]), "+f"(c[1]), "+f"(c[2]), "+f"(c[3])
        : "r"(a[0]), "r"(a[1]), "r"(a[2]), "r"(a[3]), "r"(b[0]), "r"(b[1]));
}

__device__ __forceinline__ void ldsm_x4(uint32_t* r, uint32_t addr) {
    asm volatile(
        "ldmatrix.sync.aligned.m8n8.x4.shared.b16 {%0,%1,%2,%3}, [%4];"
        : "=r"(r[0]), "=r"(r[1]), "=r"(r[2]), "=r"(r[3]) : "r"(addr));
}

__device__ __forceinline__ void ldsm_x4_t(uint32_t* r, uint32_t addr) {
    asm volatile(
        "ldmatrix.sync.aligned.m8n8.x4.trans.shared.b16 {%0,%1,%2,%3}, [%4];"
        : "=r"(r[0]), "=r"(r[1]), "=r"(r[2]), "=r"(r[3]) : "r"(addr));
}

__device__ __forceinline__ uint32_t s2u(const void* p) {
    return (uint32_t)__cvta_generic_to_shared(p);
}

__device__ __forceinline__ void cpa16(uint32_t dst, const void* src) {
    asm volatile("cp.async.cg.shared.global [%0], [%1], 16;"
                 :: "r"(dst), "l"(src));
}
__device__ __forceinline__ void cp_commit() {
    asm volatile("cp.async.commit_group;");
}
__device__ __forceinline__ void cp_wait0() {
    asm volatile("cp.async.wait_group 0;");
}

__device__ __forceinline__ uint32_t pack_hi2(float x, float y) {
    __nv_bfloat162 h = __float22bfloat162_rn(make_float2(x, y));
    return *(uint32_t*)&h;
}
__device__ __forceinline__ uint32_t pack_lo2(float x, float y, uint32_t hi) {
    __nv_bfloat162 h = *(__nv_bfloat162*)&hi;
    float2 r = __bfloat1622float2(h);
    __nv_bfloat162 l = __float22bfloat162_rn(make_float2(x - r.x, y - r.y));
    return *(uint32_t*)&l;
}

// ======================================================================
// Input splitter: x + 4 weight matrices -> persistent bf16 hi/lo arrays.
// One launch; float4-vectorized; runs once per call (deterministic).
// ======================================================================
#define NX4 (M_ * D_ / 4)
#define NW4 (D_ * D_ / 4)

__global__ void __launch_bounds__(256)
split_kernel(const float* __restrict__ x,
             const float* __restrict__ wq, const float* __restrict__ wk,
             const float* __restrict__ wv, const float* __restrict__ wo) {
    const int idx = blockIdx.x * 256 + threadIdx.x;   // float4 units
    if (idx >= NX4 + 4 * NW4) return;
    const float* src;
    bf16 *hi, *lo;
    int off;
    if (idx < NX4) {
        src = x; hi = g_xh; lo = g_xl; off = idx;
    } else {
        const int t = (idx - NX4) / NW4;
        off = (idx - NX4) % NW4;
        src = (t == 0) ? wq : (t == 1) ? wk : (t == 2) ? wv : wo;
        hi = g_wh + (size_t)t * D_ * D_;
        lo = g_wl + (size_t)t * D_ * D_;
    }
    float4 v = ((const float4*)src)[off];
    uint32_t h01 = pack_hi2(v.x, v.y);
    uint32_t h23 = pack_hi2(v.z, v.w);
    uint32_t l01 = pack_lo2(v.x, v.y, h01);
    uint32_t l23 = pack_lo2(v.z, v.w, h23);
    *(uint2*)(hi + 4 * (size_t)off) = make_uint2(h01, h23);
    *(uint2*)(lo + 4 * (size_t)off) = make_uint2(l01, l23);
}

// ======================================================================
// RoPE table.
// ======================================================================
__global__ void __launch_bounds__(256)
rope_table_kernel() {
    const int idx = blockIdx.x * 256 + threadIdx.x;
    if (idx >= L_ * 32) return;
    const int pos = idx >> 5, f = idx & 31;
    const float inv_freq = (float)exp(-(double)f * 0.28782313662425572);  // ln(1e4)/32
    const float theta = (float)pos * inv_freq;
    float s, c;
    sincosf(theta, &s, &c);
    g_rcos[idx] = c;
    g_rsin[idx] = s;
}

// ======================================================================
// bf16-split GEMM (NT): C = A W^T via Ah*Wh + Ah*Wl + Al*Wh.
// Operands PRE-SPLIT bf16; tiles loaded with cp.async; zero conversions
// in the mainloop. Block 128x128, 8 warps (4x2), BK=32, double buffer.
// mode=1: RoPE epilogue (z<2) + bf16 hi/lo output. mode=0: fp32 output.
// ======================================================================
#define GS_STRIDE 40                          // bf16 per smem row (padded)
#define GS_TILE_B (128 * GS_STRIDE * 2)       // 10240 B per sub-tile
#define GS_BUF_B  (4 * GS_TILE_B)             // Ah,Al,Wh,Wl = 40960 B
#define GSMEM     (2 * GS_BUF_B)              // 81920 B

__global__ void __launch_bounds__(256, 2)
gemm_tc_kernel(const bf16* __restrict__ Ah_g, const bf16* __restrict__ Al_g,
               const bf16* __restrict__ Wh_g, const bf16* __restrict__ Wl_g,
               bf16* __restrict__ Oh, bf16* __restrict__ Ol,
               float* __restrict__ Cf, int mode) {
    extern __shared__ char gsm[];
    const int z = blockIdx.z;

    const int tid = threadIdx.x;
    const int wid = tid >> 5, lane = tid & 31;
    const int bm = blockIdx.y * 128;
    const int bn = blockIdx.x * 128;
    const int wm = (wid >> 1) * 32;
    const int wn = (wid & 1) * 64;
    const int qid = lane >> 2;
    const int tq  = lane & 3;

    // per-z operand/output bases
    const bf16* bases[4] = {
        Ah_g + (size_t)bm * D_,
        Al_g + (size_t)bm * D_,
        Wh_g + (size_t)z * D_ * D_ + (size_t)bn * D_,
        Wl_g + (size_t)z * D_ * D_ + (size_t)bn * D_
    };
    bf16* Ohz = Oh + (size_t)z * M_ * D_;
    bf16* Olz = Ol + (size_t)z * M_ * D_;

    // ldmatrix lane address components (element units)
    const int rowa = (lane & 7) + (((lane >> 3) & 1) << 3);   // A x4
    const int cola = (lane >> 4) << 3;
    const int roww = (lane & 7) + ((lane >> 4) << 3);         // W x4
    const int colw = ((lane >> 3) & 1) << 3;

    float acc[2][8][4];
#pragma unroll
    for (int mi = 0; mi < 2; mi++)
#pragma unroll
        for (int ni = 0; ni < 8; ni++)
#pragma unroll
            for (int j = 0; j < 4; j++) acc[mi][ni][j] = 0.f;

    const uint32_t ub0 = s2u(gsm);

    // issue all 4 tiles of chunk ch into buffer (ch&1) via cp.async
    auto issue = [&](int ch) {
        const uint32_t ub = ub0 + (ch & 1) * GS_BUF_B;
        const int k0 = ch * 32;
#pragma unroll
        for (int i = 0; i < 8; i++) {
            const int idx = tid + i * 256;     // [0,2048)
            const int t = idx >> 9;            // tile 0..3
            const int rem = idx & 511;
            const int r = rem >> 2;            // row 0..127
            const int seg = rem & 3;           // 16B segment
            cpa16(ub + t * GS_TILE_B + (r * GS_STRIDE + seg * 8) * 2,
                  bases[t] + (size_t)r * D_ + k0 + seg * 8);
        }
    };

    issue(0);
    cp_commit();

    for (int ch = 0; ch < D_ / 32; ch++) {
        cp_wait0();
        __syncthreads();
        if (ch + 1 < D_ / 32) { issue(ch + 1); cp_commit(); }

        const uint32_t ub = ub0 + (ch & 1) * GS_BUF_B;
        const uint32_t uAh = ub;
        const uint32_t uAl = ub + GS_TILE_B;
        const uint32_t uWh = ub + 2 * GS_TILE_B;
        const uint32_t uWl = ub + 3 * GS_TILE_B;

#pragma unroll
        for (int ks = 0; ks < 2; ks++) {
            const int kb = ks * 16;
            uint32_t ah[2][4], al[2][4];
#pragma unroll
            for (int mi = 0; mi < 2; mi++) {
                const uint32_t aoff =
                    (uint32_t)(((wm + mi * 16 + rowa) * GS_STRIDE + kb + cola) * 2);
                ldsm_x4(ah[mi], uAh + aoff);
                ldsm_x4(al[mi], uAl + aoff);
            }
#pragma unroll
            for (int nip = 0; nip < 4; nip++) {
                const uint32_t woff =
                    (uint32_t)(((wn + nip * 16 + roww) * GS_STRIDE + kb + colw) * 2);
                uint32_t wh4[4], wl4[4];
                ldsm_x4(wh4, uWh + woff);
                ldsm_x4(wl4, uWl + woff);
#pragma unroll
                for (int mi = 0; mi < 2; mi++) {
                    mma16816(acc[mi][2 * nip],     ah[mi], wh4);       // hi*hi
                    mma16816(acc[mi][2 * nip + 1], ah[mi], wh4 + 2);
                    mma16816(acc[mi][2 * nip],     ah[mi], wl4);       // hi*lo
                    mma16816(acc[mi][2 * nip + 1], ah[mi], wl4 + 2);
                    mma16816(acc[mi][2 * nip],     al[mi], wh4);       // lo*hi
                    mma16816(acc[mi][2 * nip + 1], al[mi], wh4 + 2);
                }
            }
        }
    }

    if (mode) {
        // ---- fused RoPE (q/k only): pair (f, f+32) = (ni, ni+4) ----
        if (z < 2) {
            const float qs = (z == 0) ? 0.125f : 1.0f;
#pragma unroll
            for (int mi = 0; mi < 2; mi++) {
                const int r0 = bm + wm + mi * 16 + qid;
                const int pos0 = r0 & (L_ - 1);
                const int pos1 = (r0 + 8) & (L_ - 1);
#pragma unroll
                for (int ni = 0; ni < 4; ni++) {
#pragma unroll
                    for (int e = 0; e < 2; e++) {
                        const int f = ni * 8 + tq * 2 + e;
                        const float c0v = g_rcos[pos0 * 32 + f];
                        const float s0v = g_rsin[pos0 * 32 + f];
                        const float c1v = g_rcos[pos1 * 32 + f];
                        const float s1v = g_rsin[pos1 * 32 + f];
                        float x0 = acc[mi][ni][e],     y0 = acc[mi][ni + 4][e];
                        float x1 = acc[mi][ni][e + 2], y1 = acc[mi][ni + 4][e + 2];
                        acc[mi][ni][e]         = (x0 * c0v - y0 * s0v) * qs;
                        acc[mi][ni + 4][e]     = (y0 * c0v + x0 * s0v) * qs;
                        acc[mi][ni][e + 2]     = (x1 * c1v - y1 * s1v) * qs;
                        acc[mi][ni + 4][e + 2] = (y1 * c1v + x1 * s1v) * qs;
                    }
                }
            }
        }
        // ---- bf16 hi/lo output ----
#pragma unroll
        for (int mi = 0; mi < 2; mi++) {
            const size_t row0 = (size_t)(bm + wm + mi * 16 + qid) * D_;
            const size_t row1 = row0 + 8 * (size_t)D_;
#pragma unroll
            for (int ni = 0; ni < 8; ni++) {
                const int col = bn + wn + ni * 8 + tq * 2;
                uint32_t h0 = pack_hi2(acc[mi][ni][0], acc[mi][ni][1]);
                uint32_t l0 = pack_lo2(acc[mi][ni][0], acc[mi][ni][1], h0);
                uint32_t h1 = pack_hi2(acc[mi][ni][2], acc[mi][ni][3]);
                uint32_t l1 = pack_lo2(acc[mi][ni][2], acc[mi][ni][3], h1);
                *(uint32_t*)(Ohz + row0 + col) = h0;
                *(uint32_t*)(Olz + row0 + col) = l0;
                *(uint32_t*)(Ohz + row1 + col) = h1;
                *(uint32_t*)(Olz + row1 + col) = l1;
            }
        }
    } else {
        // ---- fp32 output (final projection) ----
#pragma unroll
        for (int mi = 0; mi < 2; mi++) {
            const int row = bm + wm + mi * 16 + qid;
#pragma unroll
            for (int ni = 0; ni < 8; ni++) {
                const int col = bn + wn + ni * 8 + tq * 2;
                *(float2*)(Cf + (size_t)row * D_ + col) =
                    make_float2(acc[mi][ni][0], acc[mi][ni][1]);
                *(float2*)(Cf + (size_t)(row + 8) * D_ + col) =
                    make_float2(acc[mi][ni][2], acc[mi][ni][3]);
            }
        }
    }
}

// ======================================================================
// Flash attention on mma.sync, bf16-split both matmuls. All operands
// pre-split bf16; K/V tiles via cp.async; zero conversions except the
// inherent P pack. Block = (b,h) x 128 q-rows, 8 warps x 16 q-rows.
// KV tiles of 64, double buffer, one barrier per tile.
// ======================================================================
#define AST     72                        // bf16 stride (conflict-free LDSM)
#define ATILE_B (64 * AST * 2)            // 9216 B per sub-tile
#define ABUF    (4 * ATILE_B)             // Kh,Kl,Vh,Vl = 36864 B
#define ASMEM   (2 * ABUF)                // 73728 B

__global__ void __launch_bounds__(256, 1)
attn_kernel(const bf16* __restrict__ qkvh, const bf16* __restrict__ qkvl,
            bf16* __restrict__ oh, bf16* __restrict__ ol) {
    extern __shared__ char asmem[];

    const int qt  = blockIdx.x;            // q tile of 128
    const int bh  = blockIdx.y;
    const int b   = bh >> 4;
    const int h   = bh & 15;
    const int tid = threadIdx.x;
    const int warp = tid >> 5, lane = tid & 31;
    const int qid = lane >> 2, tq = lane & 3;
    const int wq = warp * 16;

    // ldmatrix lane address components
    const int rowk = (lane & 7) + ((lane >> 4) << 3);         // K x4 (B, non-trans)
    const int colk = ((lane >> 3) & 1) << 3;
    const int rowv = (lane & 7) + (((lane >> 3) & 1) << 3);   // V x4 trans
    const int colv = (lane >> 4) << 3;

    const size_t hb = (size_t)b * L_ * D_ + h * HD_;
    const bf16* kv_bases[4] = {
        qkvh + (size_t)M_ * D_ + hb,          // Kh
        qkvl + (size_t)M_ * D_ + hb,          // Kl
        qkvh + 2 * (size_t)M_ * D_ + hb,      // Vh
        qkvl + 2 * (size_t)M_ * D_ + hb       // Vl
    };

    // ---- Q fragments (pre-split; register-resident) ----
    const bf16* qh_r0 = qkvh + hb + (size_t)(qt * 128 + wq + qid) * D_;
    const bf16* ql_r0 = qkvl + hb + (size_t)(qt * 128 + wq + qid) * D_;
    uint32_t qh[4][4], ql[4][4];
#pragma unroll
    for (int t = 0; t < 4; t++) {
        const int c0 = t * 16 + 2 * tq;
        qh[t][0] = *(const uint32_t*)(qh_r0 + c0);
        qh[t][1] = *(const uint32_t*)(qh_r0 + 8 * D_ + c0);
        qh[t][2] = *(const uint32_t*)(qh_r0 + c0 + 8);
        qh[t][3] = *(const uint32_t*)(qh_r0 + 8 * D_ + c0 + 8);
        ql[t][0] = *(const uint32_t*)(ql_r0 + c0);
        ql[t][1] = *(const uint32_t*)(ql_r0 + 8 * D_ + c0);
        ql[t][2] = *(const uint32_t*)(ql_r0 + c0 + 8);
        ql[t][3] = *(const uint32_t*)(ql_r0 + 8 * D_ + c0 + 8);
    }

    float oc[8][4];
#pragma unroll
    for (int j = 0; j < 8; j++)
#pragma unroll
        for (int c = 0; c < 4; c++) oc[j][c] = 0.f;
    float m0 = -1e30f, m1 = -1e30f, l0 = 0.f, l1 = 0.f;

    const uint32_t ub0 = s2u(asmem);

    auto issue = [&](int ch) {
        const uint32_t ub = ub0 + (ch & 1) * ABUF;
#pragma unroll
        for (int i = 0; i < 8; i++) {
            const int idx = tid + i * 256;     // [0,2048)
            const int t = idx >> 9;            // tile 0..3
            const int rem = idx & 511;
            const int r = rem >> 3;            // kv row 0..63
            const int seg = rem & 7;           // 16B segment (64 bf16/row)
            cpa16(ub + t * ATILE_B + (r * AST + seg * 8) * 2,
                  kv_bases[t] + (size_t)(ch * 64 + r) * D_ + seg * 8);
        }
    };

    issue(0);
    cp_commit();

    for (int ch = 0; ch < L_ / 64; ch++) {
        cp_wait0();
        __syncthreads();
        if (ch + 1 < L_ / 64) { issue(ch + 1); cp_commit(); }

        const uint32_t ub = ub0 + (ch & 1) * ABUF;
        const uint32_t uKh = ub;
        const uint32_t uKl = ub + ATILE_B;
        const uint32_t uVh = ub + 2 * ATILE_B;
        const uint32_t uVl = ub + 3 * ATILE_B;

        // ---- S = Q K^T (3-term split) ----
        float sc[8][4];
#pragma unroll
        for (int j = 0; j < 8; j++)
#pragma unroll
            for (int c = 0; c < 4; c++) sc[j][c] = 0.f;

#pragma unroll
        for (int t = 0; t < 4; t++) {
#pragma unroll
            for (int jp = 0; jp < 4; jp++) {
                const uint32_t koff =
                    (uint32_t)(((jp * 16 + rowk) * AST + t * 16 + colk) * 2);
                uint32_t bh4[4], bl4[4];
                ldsm_x4(bh4, uKh + koff);
                ldsm_x4(bl4, uKl + koff);
                mma16816(sc[2 * jp],     qh[t], bh4);       // hi*hi
                mma16816(sc[2 * jp + 1], qh[t], bh4 + 2);
                mma16816(sc[2 * jp],     qh[t], bl4);       // hi*lo
                mma16816(sc[2 * jp + 1], qh[t], bl4 + 2);
                mma16816(sc[2 * jp],     ql[t], bh4);       // lo*hi
                mma16816(sc[2 * jp + 1], ql[t], bh4 + 2);
            }
        }

        // ---- online softmax (register fragments) ----
        float mx0 = -1e30f, mx1 = -1e30f;
#pragma unroll
        for (int j = 0; j < 8; j++) {
            mx0 = fmaxf(mx0, fmaxf(sc[j][0], sc[j][1]));
            mx1 = fmaxf(mx1, fmaxf(sc[j][2], sc[j][3]));
        }
        mx0 = fmaxf(mx0, __shfl_xor_sync(0xffffffffu, mx0, 1));
        mx0 = fmaxf(mx0, __shfl_xor_sync(0xffffffffu, mx0, 2));
        mx1 = fmaxf(mx1, __shfl_xor_sync(0xffffffffu, mx1, 1));
        mx1 = fmaxf(mx1, __shfl_xor_sync(0xffffffffu, mx1, 2));

        const float mn0 = fmaxf(m0, mx0), mn1 = fmaxf(m1, mx1);
        const float al0 = __expf(m0 - mn0), al1 = __expf(m1 - mn1);
        float sum0 = 0.f, sum1 = 0.f;
#pragma unroll
        for (int j = 0; j < 8; j++) {
            sc[j][0] = __expf(sc[j][0] - mn0);
            sc[j][1] = __expf(sc[j][1] - mn0);
            sc[j][2] = __expf(sc[j][2] - mn1);
            sc[j][3] = __expf(sc[j][3] - mn1);
            sum0 += sc[j][0] + sc[j][1];
            sum1 += sc[j][2] + sc[j][3];
        }
        sum0 += __shfl_xor_sync(0xffffffffu, sum0, 1);
        sum0 += __shfl_xor_sync(0xffffffffu, sum0, 2);
        sum1 += __shfl_xor_sync(0xffffffffu, sum1, 1);
        sum1 += __shfl_xor_sync(0xffffffffu, sum1, 2);
        l0 = l0 * al0 + sum0;  m0 = mn0;
        l1 = l1 * al1 + sum1;  m1 = mn1;
#pragma unroll
        for (int j = 0; j < 8; j++) {
            oc[j][0] *= al0; oc[j][1] *= al0;
            oc[j][2] *= al1; oc[j][3] *= al1;
        }

        // ---- O += P V (3-term split); V frags via ldmatrix.trans ----
#pragma unroll
        for (int t = 0; t < 4; t++) {
            const int j0 = 2 * t, j1 = 2 * t + 1;
            uint32_t ph[4], pl[4];
            ph[0] = pack_hi2(sc[j0][0], sc[j0][1]); pl[0] = pack_lo2(sc[j0][0], sc[j0][1], ph[0]);
            ph[1] = pack_hi2(sc[j0][2], sc[j0][3]); pl[1] = pack_lo2(sc[j0][2], sc[j0][3], ph[1]);
            ph[2] = pack_hi2(sc[j1][0], sc[j1][1]); pl[2] = pack_lo2(sc[j1][0], sc[j1][1], ph[2]);
            ph[3] = pack_hi2(sc[j1][2], sc[j1][3]); pl[3] = pack_lo2(sc[j1][2], sc[j1][3], ph[3]);

#pragma unroll
            for (int jp = 0; jp < 4; jp++) {
                const uint32_t voff =
                    (uint32_t)(((t * 16 + rowv) * AST + jp * 16 + colv) * 2);
                uint32_t vh4[4], vl4[4];
                ldsm_x4_t(vh4, uVh + voff);
                ldsm_x4_t(vl4, uVl + voff);
                mma16816(oc[2 * jp],     ph, vh4);          // hi*hi
                mma16816(oc[2 * jp + 1], ph, vh4 + 2);
                mma16816(oc[2 * jp],     ph, vl4);          // hi*lo
                mma16816(oc[2 * jp + 1], ph, vl4 + 2);
                mma16816(oc[2 * jp],     pl, vh4);          // lo*hi
                mma16816(oc[2 * jp + 1], pl, vh4 + 2);
            }
        }
        __syncthreads();
    }

    // ---- epilogue: normalize, split to hi/lo bf16 for the Wo gemm ----
    const float inv0 = 1.f / l0, inv1 = 1.f / l1;
    const size_t row0 = (size_t)(b * L_ + qt * 128 + wq + qid) * D_ + h * HD_;
    const size_t row1 = row0 + 8 * (size_t)D_;
#pragma unroll
    for (int j = 0; j < 8; j++) {
        const int col = j * 8 + 2 * tq;
        float v00 = oc[j][0] * inv0, v01 = oc[j][1] * inv0;
        float v10 = oc[j][2] * inv1, v11 = oc[j][3] * inv1;
        uint32_t h0 = pack_hi2(v00, v01);
        uint32_t l0w = pack_lo2(v00, v01, h0);
        uint32_t h1 = pack_hi2(v10, v11);
        uint32_t l1w = pack_lo2(v10, v11, h1);
        *(uint32_t*)(oh + row0 + col) = h0;
        *(uint32_t*)(ol + row0 + col) = l0w;
        *(uint32_t*)(oh + row1 + col) = h1;
        *(uint32_t*)(ol + row1 + col) = l1w;
    }
}

// ======================================================================
// launcher
// ======================================================================
extern "C" void kernel_launch(void* const* d_in, const int* in_sizes, int n_in,
                              void* d_out, int out_size) {
    const float* x  = (const float*)d_in[0];
    const float* Wq = (const float*)d_in[1];
    const float* Wk = (const float*)d_in[2];
    const float* Wv = (const float*)d_in[3];
    const float* Wo = (const float*)d_in[4];
    float* out = (float*)d_out;

    bf16 *xh, *xl, *wh, *wl, *qkvh, *qkvl, *oh, *ol;
    cudaGetSymbolAddress((void**)&xh, g_xh);
    cudaGetSymbolAddress((void**)&xl, g_xl);
    cudaGetSymbolAddress((void**)&wh, g_wh);
    cudaGetSymbolAddress((void**)&wl, g_wl);
    cudaGetSymbolAddress((void**)&qkvh, g_qkvh);
    cudaGetSymbolAddress((void**)&qkvl, g_qkvl);
    cudaGetSymbolAddress((void**)&oh, g_oh);
    cudaGetSymbolAddress((void**)&ol, g_ol);

    cudaFuncSetAttribute(gemm_tc_kernel, cudaFuncAttributeMaxDynamicSharedMemorySize,
                         GSMEM);
    cudaFuncSetAttribute(attn_kernel, cudaFuncAttributeMaxDynamicSharedMemorySize,
                         ASMEM);

    rope_table_kernel<<<(L_ * 32 + 255) / 256, 256>>>();
    split_kernel<<<(NX4 + 4 * NW4 + 255) / 256, 256>>>(x, Wq, Wk, Wv, Wo);

    // fused QKV projection (+RoPE), bf16 hi/lo outputs
    gemm_tc_kernel<<<dim3(D_ / 128, M_ / 128, 3), 256, GSMEM>>>(
        xh, xl, wh, wl, qkvh, qkvl, nullptr, 1);

    attn_kernel<<<dim3(L_ / 128, B_ * H_), 256, ASMEM>>>(qkvh, qkvl, oh, ol);

    // output projection (weights slot 3), fp32 output
    gemm_tc_kernel<<<dim3(D_ / 128, M_ / 128, 1), 256, GSMEM>>>(
        oh, ol, wh + 3 * (size_t)D_ * D_, wl + 3 * (size_t)D_ * D_,
        nullptr, nullptr, out, 0);
}

// round 17
// speedup vs baseline: 1.0342x; 1.0342x over previous
#include <cuda_runtime.h>
#include <cuda_bf16.h>
#include <math.h>
#include <stdint.h>

typedef __nv_bfloat16 bf16;

// ---------------- problem constants ----------------
#define B_  4
#define L_  2048
#define D_  1024
#define H_  16
#define HD_ 64
#define M_  (B_ * L_)          // 8192 rows

// ---------------- scratch (device globals; no allocs allowed) ----------------
__device__ __align__(256) bf16 g_xh[(size_t)M_ * D_];
__device__ __align__(256) bf16 g_xl[(size_t)M_ * D_];
__device__ __align__(256) bf16 g_wh[4 * (size_t)D_ * D_];
__device__ __align__(256) bf16 g_wl[4 * (size_t)D_ * D_];
__device__ __align__(256) bf16 g_qkvh[3 * (size_t)M_ * D_];
__device__ __align__(256) bf16 g_qkvl[3 * (size_t)M_ * D_];
__device__ __align__(256) bf16 g_oh[(size_t)M_ * D_];
__device__ __align__(256) bf16 g_ol[(size_t)M_ * D_];
__device__ float g_rcos[L_ * 32];
__device__ float g_rsin[L_ * 32];

// ---------------- base-ISA mma/ldmatrix/cp.async helpers ----------------
__device__ __forceinline__ void mma16816(float* c, const uint32_t* a,
                                         const uint32_t* b) {
    asm volatile(
        "mma.sync.aligned.m16n8k16.row.col.f32.bf16.bf16.f32 "
        "{%0,%1,%2,%3}, {%4,%5,%6,%7}, {%8,%9}, {%0,%1,%2,%3};"
        : "+f"(c[0]), "+f"(c[1]), "+f"(c[2]), "+f"(c[3])
        : "r"(a[0]), "r"(a[1]), "r"(a[2]), "r"(a[3]), "r"(b[0]), "r"(b[1]));
}

__device__ __forceinline__ void ldsm_x4(uint32_t* r, uint32_t addr) {
    asm volatile(
        "ldmatrix.sync.aligned.m8n8.x4.shared.b16 {%0,%1,%2,%3}, [%4];"
        : "=r"(r[0]), "=r"(r[1]), "=r"(r[2]), "=r"(r[3]) : "r"(addr));
}

__device__ __forceinline__ void ldsm_x4_t(uint32_t* r, uint32_t addr) {
    asm volatile(
        "ldmatrix.sync.aligned.m8n8.x4.trans.shared.b16 {%0,%1,%2,%3}, [%4];"
        : "=r"(r[0]), "=r"(r[1]), "=r"(r[2]), "=r"(r[3]) : "r"(addr));
}

__device__ __forceinline__ uint32_t s2u(const void* p) {
    return (uint32_t)__cvta_generic_to_shared(p);
}

__device__ __forceinline__ void cpa16(uint32_t dst, const void* src) {
    asm volatile("cp.async.cg.shared.global [%0], [%1], 16;"
                 :: "r"(dst), "l"(src));
}
__device__ __forceinline__ void cp_commit() {
    asm volatile("cp.async.commit_group;");
}
__device__ __forceinline__ void cp_wait0() {
    asm volatile("cp.async.wait_group 0;");
}

__device__ __forceinline__ uint32_t pack_hi2(float x, float y) {
    __nv_bfloat162 h = __float22bfloat162_rn(make_float2(x, y));
    return *(uint32_t*)&h;
}
__device__ __forceinline__ uint32_t pack_lo2(float x, float y, uint32_t hi) {
    __nv_bfloat162 h = *(__nv_bfloat162*)&hi;
    float2 r = __bfloat1622float2(h);
    __nv_bfloat162 l = __float22bfloat162_rn(make_float2(x - r.x, y - r.y));
    return *(uint32_t*)&l;
}

// ======================================================================
// Input splitter: x + 4 weight matrices -> persistent bf16 hi/lo arrays.
// ======================================================================
#define NX4 (M_ * D_ / 4)
#define NW4 (D_ * D_ / 4)

__global__ void __launch_bounds__(256)
split_kernel(const float* __restrict__ x,
             const float* __restrict__ wq, const float* __restrict__ wk,
             const float* __restrict__ wv, const float* __restrict__ wo) {
    const int idx = blockIdx.x * 256 + threadIdx.x;   // float4 units
    if (idx >= NX4 + 4 * NW4) return;
    const float* src;
    bf16 *hi, *lo;
    int off;
    if (idx < NX4) {
        src = x; hi = g_xh; lo = g_xl; off = idx;
    } else {
        const int t = (idx - NX4) / NW4;
        off = (idx - NX4) % NW4;
        src = (t == 0) ? wq : (t == 1) ? wk : (t == 2) ? wv : wo;
        hi = g_wh + (size_t)t * D_ * D_;
        lo = g_wl + (size_t)t * D_ * D_;
    }
    float4 v = ((const float4*)src)[off];
    uint32_t h01 = pack_hi2(v.x, v.y);
    uint32_t h23 = pack_hi2(v.z, v.w);
    uint32_t l01 = pack_lo2(v.x, v.y, h01);
    uint32_t l23 = pack_lo2(v.z, v.w, h23);
    *(uint2*)(hi + 4 * (size_t)off) = make_uint2(h01, h23);
    *(uint2*)(lo + 4 * (size_t)off) = make_uint2(l01, l23);
}

// ======================================================================
// RoPE table.
// ======================================================================
__global__ void __launch_bounds__(256)
rope_table_kernel() {
    const int idx = blockIdx.x * 256 + threadIdx.x;
    if (idx >= L_ * 32) return;
    const int pos = idx >> 5, f = idx & 31;
    const float inv_freq = (float)exp(-(double)f * 0.28782313662425572);  // ln(1e4)/32
    const float theta = (float)pos * inv_freq;
    float s, c;
    sincosf(theta, &s, &c);
    g_rcos[idx] = c;
    g_rsin[idx] = s;
}

// ======================================================================
// bf16-split GEMM (NT): C = A W^T via Ah*Wh + Ah*Wl + Al*Wh.
// Pre-split operands, cp.async tiles, product-major mma order
// (accumulator reuse distance 4). Block 128x128, 8 warps, BK=32.
// ======================================================================
#define GS_STRIDE 40                          // bf16 per smem row (padded)
#define GS_TILE_B (128 * GS_STRIDE * 2)       // 10240 B per sub-tile
#define GS_BUF_B  (4 * GS_TILE_B)             // Ah,Al,Wh,Wl = 40960 B
#define GSMEM     (2 * GS_BUF_B)              // 81920 B

__global__ void __launch_bounds__(256, 2)
gemm_tc_kernel(const bf16* __restrict__ Ah_g, const bf16* __restrict__ Al_g,
               const bf16* __restrict__ Wh_g, const bf16* __restrict__ Wl_g,
               bf16* __restrict__ Oh, bf16* __restrict__ Ol,
               float* __restrict__ Cf, int mode) {
    extern __shared__ char gsm[];
    const int z = blockIdx.z;

    const int tid = threadIdx.x;
    const int wid = tid >> 5, lane = tid & 31;
    const int bm = blockIdx.y * 128;
    const int bn = blockIdx.x * 128;
    const int wm = (wid >> 1) * 32;
    const int wn = (wid & 1) * 64;
    const int qid = lane >> 2;
    const int tq  = lane & 3;

    const bf16* bases[4] = {
        Ah_g + (size_t)bm * D_,
        Al_g + (size_t)bm * D_,
        Wh_g + (size_t)z * D_ * D_ + (size_t)bn * D_,
        Wl_g + (size_t)z * D_ * D_ + (size_t)bn * D_
    };
    bf16* Ohz = Oh + (size_t)z * M_ * D_;
    bf16* Olz = Ol + (size_t)z * M_ * D_;

    const int rowa = (lane & 7) + (((lane >> 3) & 1) << 3);   // A x4
    const int cola = (lane >> 4) << 3;
    const int roww = (lane & 7) + ((lane >> 4) << 3);         // W x4
    const int colw = ((lane >> 3) & 1) << 3;

    float acc[2][8][4];
#pragma unroll
    for (int mi = 0; mi < 2; mi++)
#pragma unroll
        for (int ni = 0; ni < 8; ni++)
#pragma unroll
            for (int j = 0; j < 4; j++) acc[mi][ni][j] = 0.f;

    const uint32_t ub0 = s2u(gsm);

    auto issue = [&](int ch) {
        const uint32_t ub = ub0 + (ch & 1) * GS_BUF_B;
        const int k0 = ch * 32;
#pragma unroll
        for (int i = 0; i < 8; i++) {
            const int idx = tid + i * 256;
            const int t = idx >> 9;
            const int rem = idx & 511;
            const int r = rem >> 2;
            const int seg = rem & 3;
            cpa16(ub + t * GS_TILE_B + (r * GS_STRIDE + seg * 8) * 2,
                  bases[t] + (size_t)r * D_ + k0 + seg * 8);
        }
    };

    issue(0);
    cp_commit();

    for (int ch = 0; ch < D_ / 32; ch++) {
        cp_wait0();
        __syncthreads();
        if (ch + 1 < D_ / 32) { issue(ch + 1); cp_commit(); }

        const uint32_t ub = ub0 + (ch & 1) * GS_BUF_B;
        const uint32_t uAh = ub;
        const uint32_t uAl = ub + GS_TILE_B;
        const uint32_t uWh = ub + 2 * GS_TILE_B;
        const uint32_t uWl = ub + 3 * GS_TILE_B;

#pragma unroll
        for (int ks = 0; ks < 2; ks++) {
            const int kb = ks * 16;
            uint32_t ah[2][4], al[2][4];
#pragma unroll
            for (int mi = 0; mi < 2; mi++) {
                const uint32_t aoff =
                    (uint32_t)(((wm + mi * 16 + rowa) * GS_STRIDE + kb + cola) * 2);
                ldsm_x4(ah[mi], uAh + aoff);
                ldsm_x4(al[mi], uAl + aoff);
            }
#pragma unroll
            for (int nip = 0; nip < 4; nip++) {
                const uint32_t woff =
                    (uint32_t)(((wn + nip * 16 + roww) * GS_STRIDE + kb + colw) * 2);
                uint32_t wh4[4], wl4[4];
                ldsm_x4(wh4, uWh + woff);
                ldsm_x4(wl4, uWl + woff);
                // product-major: same accumulator reused at distance 4
                mma16816(acc[0][2 * nip],     ah[0], wh4);        // hi*hi
                mma16816(acc[0][2 * nip + 1], ah[0], wh4 + 2);
                mma16816(acc[1][2 * nip],     ah[1], wh4);
                mma16816(acc[1][2 * nip + 1], ah[1], wh4 + 2);
                mma16816(acc[0][2 * nip],     ah[0], wl4);        // hi*lo
                mma16816(acc[0][2 * nip + 1], ah[0], wl4 + 2);
                mma16816(acc[1][2 * nip],     ah[1], wl4);
                mma16816(acc[1][2 * nip + 1], ah[1], wl4 + 2);
                mma16816(acc[0][2 * nip],     al[0], wh4);        // lo*hi
                mma16816(acc[0][2 * nip + 1], al[0], wh4 + 2);
                mma16816(acc[1][2 * nip],     al[1], wh4);
                mma16816(acc[1][2 * nip + 1], al[1], wh4 + 2);
            }
        }
    }

    if (mode) {
        if (z < 2) {
            const float qs = (z == 0) ? 0.125f : 1.0f;
#pragma unroll
            for (int mi = 0; mi < 2; mi++) {
                const int r0 = bm + wm + mi * 16 + qid;
                const int pos0 = r0 & (L_ - 1);
                const int pos1 = (r0 + 8) & (L_ - 1);
#pragma unroll
                for (int ni = 0; ni < 4; ni++) {
#pragma unroll
                    for (int e = 0; e < 2; e++) {
                        const int f = ni * 8 + tq * 2 + e;
                        const float c0v = g_rcos[pos0 * 32 + f];
                        const float s0v = g_rsin[pos0 * 32 + f];
                        const float c1v = g_rcos[pos1 * 32 + f];
                        const float s1v = g_rsin[pos1 * 32 + f];
                        float x0 = acc[mi][ni][e],     y0 = acc[mi][ni + 4][e];
                        float x1 = acc[mi][ni][e + 2], y1 = acc[mi][ni + 4][e + 2];
                        acc[mi][ni][e]         = (x0 * c0v - y0 * s0v) * qs;
                        acc[mi][ni + 4][e]     = (y0 * c0v + x0 * s0v) * qs;
                        acc[mi][ni][e + 2]     = (x1 * c1v - y1 * s1v) * qs;
                        acc[mi][ni + 4][e + 2] = (y1 * c1v + x1 * s1v) * qs;
                    }
                }
            }
        }
#pragma unroll
        for (int mi = 0; mi < 2; mi++) {
            const size_t row0 = (size_t)(bm + wm + mi * 16 + qid) * D_;
            const size_t row1 = row0 + 8 * (size_t)D_;
#pragma unroll
            for (int ni = 0; ni < 8; ni++) {
                const int col = bn + wn + ni * 8 + tq * 2;
                uint32_t h0 = pack_hi2(acc[mi][ni][0], acc[mi][ni][1]);
                uint32_t l0 = pack_lo2(acc[mi][ni][0], acc[mi][ni][1], h0);
                uint32_t h1 = pack_hi2(acc[mi][ni][2], acc[mi][ni][3]);
                uint32_t l1 = pack_lo2(acc[mi][ni][2], acc[mi][ni][3], h1);
                *(uint32_t*)(Ohz + row0 + col) = h0;
                *(uint32_t*)(Olz + row0 + col) = l0;
                *(uint32_t*)(Ohz + row1 + col) = h1;
                *(uint32_t*)(Olz + row1 + col) = l1;
            }
        }
    } else {
#pragma unroll
        for (int mi = 0; mi < 2; mi++) {
            const int row = bm + wm + mi * 16 + qid;
#pragma unroll
            for (int ni = 0; ni < 8; ni++) {
                const int col = bn + wn + ni * 8 + tq * 2;
                *(float2*)(Cf + (size_t)row * D_ + col) =
                    make_float2(acc[mi][ni][0], acc[mi][ni][1]);
                *(float2*)(Cf + (size_t)(row + 8) * D_ + col) =
                    make_float2(acc[mi][ni][2], acc[mi][ni][3]);
            }
        }
    }
}

// ======================================================================
// Flash attention, bf16-split both matmuls, pre-split operands.
// LDG.128 reg-prefetch -> STS.128 (pass-through, no conversions),
// double buffer, ONE barrier per tile. Product-major mma ordering
// (accumulator reuse distance 8). Block = (b,h) x 128 q-rows.
// ======================================================================
#define AST     72                        // bf16 stride (conflict-free LDSM)
#define ATILE_B (64 * AST * 2)            // 9216 B per sub-tile
#define ABUF    (4 * ATILE_B)             // Kh,Kl,Vh,Vl = 36864 B
#define ASMEM   (2 * ABUF)                // 73728 B

__global__ void __launch_bounds__(256, 1)
attn_kernel(const bf16* __restrict__ qkvh, const bf16* __restrict__ qkvl,
            bf16* __restrict__ oh, bf16* __restrict__ ol) {
    extern __shared__ char asmem[];

    const int qt  = blockIdx.x;
    const int bh  = blockIdx.y;
    const int b   = bh >> 4;
    const int h   = bh & 15;
    const int tid = threadIdx.x;
    const int warp = tid >> 5, lane = tid & 31;
    const int qid = lane >> 2, tq = lane & 3;
    const int wq = warp * 16;

    const int rowk = (lane & 7) + ((lane >> 4) << 3);         // K x4 (B)
    const int colk = ((lane >> 3) & 1) << 3;
    const int rowv = (lane & 7) + (((lane >> 3) & 1) << 3);   // V x4 trans
    const int colv = (lane >> 4) << 3;

    const size_t hb = (size_t)b * L_ * D_ + h * HD_;
    const bf16* kv_bases[4] = {
        qkvh + (size_t)M_ * D_ + hb,          // Kh
        qkvl + (size_t)M_ * D_ + hb,          // Kl
        qkvh + 2 * (size_t)M_ * D_ + hb,      // Vh
        qkvl + 2 * (size_t)M_ * D_ + hb       // Vl
    };

    // ---- Q fragments (pre-split; register-resident) ----
    const bf16* qh_r0 = qkvh + hb + (size_t)(qt * 128 + wq + qid) * D_;
    const bf16* ql_r0 = qkvl + hb + (size_t)(qt * 128 + wq + qid) * D_;
    uint32_t qh[4][4], ql[4][4];
#pragma unroll
    for (int t = 0; t < 4; t++) {
        const int c0 = t * 16 + 2 * tq;
        qh[t][0] = *(const uint32_t*)(qh_r0 + c0);
        qh[t][1] = *(const uint32_t*)(qh_r0 + 8 * D_ + c0);
        qh[t][2] = *(const uint32_t*)(qh_r0 + c0 + 8);
        qh[t][3] = *(const uint32_t*)(qh_r0 + 8 * D_ + c0 + 8);
        ql[t][0] = *(const uint32_t*)(ql_r0 + c0);
        ql[t][1] = *(const uint32_t*)(ql_r0 + 8 * D_ + c0);
        ql[t][2] = *(const uint32_t*)(ql_r0 + c0 + 8);
        ql[t][3] = *(const uint32_t*)(ql_r0 + 8 * D_ + c0 + 8);
    }

    float oc[8][4];
#pragma unroll
    for (int j = 0; j < 8; j++)
#pragma unroll
        for (int c = 0; c < 4; c++) oc[j][c] = 0.f;
    float m0 = -1e30f, m1 = -1e30f, l0 = 0.f, l1 = 0.f;

    // ---- per-thread tile prefetch slots (8 x uint4 = 128 B) ----
    uint4 pf[8];
    auto prefetch = [&](int ch) {
#pragma unroll
        for (int i = 0; i < 8; i++) {
            const int idx = tid + i * 256;
            const int t = idx >> 9;
            const int rem = idx & 511;
            const int r = rem >> 3;
            const int seg = rem & 7;
            pf[i] = *(const uint4*)(kv_bases[t] + (size_t)(ch * 64 + r) * D_ + seg * 8);
        }
    };
    prefetch(0);

    for (int ch = 0; ch < L_ / 64; ch++) {
        char* buf = asmem + (ch & 1) * ABUF;

        // store prefetched tile (pass-through, 16B stores)
#pragma unroll
        for (int i = 0; i < 8; i++) {
            const int idx = tid + i * 256;
            const int t = idx >> 9;
            const int rem = idx & 511;
            const int r = rem >> 3;
            const int seg = rem & 7;
            *(uint4*)(buf + t * ATILE_B + (r * AST + seg * 8) * 2) = pf[i];
        }
        __syncthreads();   // single barrier per tile (double-buffer rotation)

        if (ch + 1 < L_ / 64) prefetch(ch + 1);

        const uint32_t ub = s2u(buf);
        const uint32_t uKh = ub;
        const uint32_t uKl = ub + ATILE_B;
        const uint32_t uVh = ub + 2 * ATILE_B;
        const uint32_t uVl = ub + 3 * ATILE_B;

        // ---- S = Q K^T (3-term split, product-major) ----
        float sc[8][4];
#pragma unroll
        for (int j = 0; j < 8; j++)
#pragma unroll
            for (int c = 0; c < 4; c++) sc[j][c] = 0.f;

#pragma unroll
        for (int t = 0; t < 4; t++) {
            uint32_t kh4[4][4], kl4[4][4];
#pragma unroll
            for (int jp = 0; jp < 4; jp++) {
                const uint32_t koff =
                    (uint32_t)(((jp * 16 + rowk) * AST + t * 16 + colk) * 2);
                ldsm_x4(kh4[jp], uKh + koff);
                ldsm_x4(kl4[jp], uKl + koff);
            }
#pragma unroll
            for (int jp = 0; jp < 4; jp++) {                  // hi*hi
                mma16816(sc[2 * jp],     qh[t], kh4[jp]);
                mma16816(sc[2 * jp + 1], qh[t], kh4[jp] + 2);
            }
#pragma unroll
            for (int jp = 0; jp < 4; jp++) {                  // hi*lo
                mma16816(sc[2 * jp],     qh[t], kl4[jp]);
                mma16816(sc[2 * jp + 1], qh[t], kl4[jp] + 2);
            }
#pragma unroll
            for (int jp = 0; jp < 4; jp++) {                  // lo*hi
                mma16816(sc[2 * jp],     ql[t], kh4[jp]);
                mma16816(sc[2 * jp + 1], ql[t], kh4[jp] + 2);
            }
        }

        // ---- online softmax (register fragments) ----
        float mx0 = -1e30f, mx1 = -1e30f;
#pragma unroll
        for (int j = 0; j < 8; j++) {
            mx0 = fmaxf(mx0, fmaxf(sc[j][0], sc[j][1]));
            mx1 = fmaxf(mx1, fmaxf(sc[j][2], sc[j][3]));
        }
        mx0 = fmaxf(mx0, __shfl_xor_sync(0xffffffffu, mx0, 1));
        mx0 = fmaxf(mx0, __shfl_xor_sync(0xffffffffu, mx0, 2));
        mx1 = fmaxf(mx1, __shfl_xor_sync(0xffffffffu, mx1, 1));
        mx1 = fmaxf(mx1, __shfl_xor_sync(0xffffffffu, mx1, 2));

        const float mn0 = fmaxf(m0, mx0), mn1 = fmaxf(m1, mx1);
        const float al0 = __expf(m0 - mn0), al1 = __expf(m1 - mn1);
        float sum0 = 0.f, sum1 = 0.f;
#pragma unroll
        for (int j = 0; j < 8; j++) {
            sc[j][0] = __expf(sc[j][0] - mn0);
            sc[j][1] = __expf(sc[j][1] - mn0);
            sc[j][2] = __expf(sc[j][2] - mn1);
            sc[j][3] = __expf(sc[j][3] - mn1);
            sum0 += sc[j][0] + sc[j][1];
            sum1 += sc[j][2] + sc[j][3];
        }
        sum0 += __shfl_xor_sync(0xffffffffu, sum0, 1);
        sum0 += __shfl_xor_sync(0xffffffffu, sum0, 2);
        sum1 += __shfl_xor_sync(0xffffffffu, sum1, 1);
        sum1 += __shfl_xor_sync(0xffffffffu, sum1, 2);
        l0 = l0 * al0 + sum0;  m0 = mn0;
        l1 = l1 * al1 + sum1;  m1 = mn1;
#pragma unroll
        for (int j = 0; j < 8; j++) {
            oc[j][0] *= al0; oc[j][1] *= al0;
            oc[j][2] *= al1; oc[j][3] *= al1;
        }

        // ---- O += P V (3-term split, product-major) ----
#pragma unroll
        for (int t = 0; t < 4; t++) {
            const int j0 = 2 * t, j1 = 2 * t + 1;
            uint32_t ph[4], pl[4];
            ph[0] = pack_hi2(sc[j0][0], sc[j0][1]); pl[0] = pack_lo2(sc[j0][0], sc[j0][1], ph[0]);
            ph[1] = pack_hi2(sc[j0][2], sc[j0][3]); pl[1] = pack_lo2(sc[j0][2], sc[j0][3], ph[1]);
            ph[2] = pack_hi2(sc[j1][0], sc[j1][1]); pl[2] = pack_lo2(sc[j1][0], sc[j1][1], ph[2]);
            ph[3] = pack_hi2(sc[j1][2], sc[j1][3]); pl[3] = pack_lo2(sc[j1][2], sc[j1][3], ph[3]);

            uint32_t vh4[4][4], vl4[4][4];
#pragma unroll
            for (int jp = 0; jp < 4; jp++) {
                const uint32_t voff =
                    (uint32_t)(((t * 16 + rowv) * AST + jp * 16 + colv) * 2);
                ldsm_x4_t(vh4[jp], uVh + voff);
                ldsm_x4_t(vl4[jp], uVl + voff);
            }
#pragma unroll
            for (int jp = 0; jp < 4; jp++) {                  // hi*hi
                mma16816(oc[2 * jp],     ph, vh4[jp]);
                mma16816(oc[2 * jp + 1], ph, vh4[jp] + 2);
            }
#pragma unroll
            for (int jp = 0; jp < 4; jp++) {                  // hi*lo
                mma16816(oc[2 * jp],     ph, vl4[jp]);
                mma16816(oc[2 * jp + 1], ph, vl4[jp] + 2);
            }
#pragma unroll
            for (int jp = 0; jp < 4; jp++) {                  // lo*hi
                mma16816(oc[2 * jp],     pl, vh4[jp]);
                mma16816(oc[2 * jp + 1], pl, vh4[jp] + 2);
            }
        }
        // no trailing barrier: next store targets the other buffer
    }

    // ---- epilogue: normalize, split to hi/lo bf16 for the Wo gemm ----
    const float inv0 = 1.f / l0, inv1 = 1.f / l1;
    const size_t row0 = (size_t)(b * L_ + qt * 128 + wq + qid) * D_ + h * HD_;
    const size_t row1 = row0 + 8 * (size_t)D_;
#pragma unroll
    for (int j = 0; j < 8; j++) {
        const int col = j * 8 + 2 * tq;
        float v00 = oc[j][0] * inv0, v01 = oc[j][1] * inv0;
        float v10 = oc[j][2] * inv1, v11 = oc[j][3] * inv1;
        uint32_t h0 = pack_hi2(v00, v01);
        uint32_t l0w = pack_lo2(v00, v01, h0);
        uint32_t h1 = pack_hi2(v10, v11);
        uint32_t l1w = pack_lo2(v10, v11, h1);
        *(uint32_t*)(oh + row0 + col) = h0;
        *(uint32_t*)(ol + row0 + col) = l0w;
        *(uint32_t*)(oh + row1 + col) = h1;
        *(uint32_t*)(ol + row1 + col) = l1w;
    }
}

// ======================================================================
// launcher
// ======================================================================
extern "C" void kernel_launch(void* const* d_in, const int* in_sizes, int n_in,
                              void* d_out, int out_size) {
    const float* x  = (const float*)d_in[0];
    const float* Wq = (const float*)d_in[1];
    const float* Wk = (const float*)d_in[2];
    const float* Wv = (const float*)d_in[3];
    const float* Wo = (const float*)d_in[4];
    float* out = (float*)d_out;

    bf16 *xh, *xl, *wh, *wl, *qkvh, *qkvl, *oh, *ol;
    cudaGetSymbolAddress((void**)&xh, g_xh);
    cudaGetSymbolAddress((void**)&xl, g_xl);
    cudaGetSymbolAddress((void**)&wh, g_wh);
    cudaGetSymbolAddress((void**)&wl, g_wl);
    cudaGetSymbolAddress((void**)&qkvh, g_qkvh);
    cudaGetSymbolAddress((void**)&qkvl, g_qkvl);
    cudaGetSymbolAddress((void**)&oh, g_oh);
    cudaGetSymbolAddress((void**)&ol, g_ol);

    cudaFuncSetAttribute(gemm_tc_kernel, cudaFuncAttributeMaxDynamicSharedMemorySize,
                         GSMEM);
    cudaFuncSetAttribute(attn_kernel, cudaFuncAttributeMaxDynamicSharedMemorySize,
                         ASMEM);

    rope_table_kernel<<<(L_ * 32 + 255) / 256, 256>>>();
    split_kernel<<<(NX4 + 4 * NW4 + 255) / 256, 256>>>(x, Wq, Wk, Wv, Wo);

    // fused QKV projection (+RoPE), bf16 hi/lo outputs
    gemm_tc_kernel<<<dim3(D_ / 128, M_ / 128, 3), 256, GSMEM>>>(
        xh, xl, wh, wl, qkvh, qkvl, nullptr, 1);

    attn_kernel<<<dim3(L_ / 128, B_ * H_), 256, ASMEM>>>(qkvh, qkvl, oh, ol);

    // output projection (weights slot 3), fp32 output
    gemm_tc_kernel<<<dim3(D_ / 128, M_ / 128, 1), 256, GSMEM>>>(
        oh, ol, wh + 3 * (size_t)D_ * D_, wl + 3 * (size_t)D_ * D_,
        nullptr, nullptr, out, 0);
}